// round 10
// baseline (speedup 1.0000x reference)
#include <cuda_runtime.h>
#include <cstdint>

// Problem constants (fixed by the reference).
#define T_DIM 100
#define NE    16777216u      // B*N*N
#define HALF  8388608u       // NE/2
#define HQ    2097152u       // HALF/4  (int4-index space of the low half)

#define THREADS 128
#define NCTA    10
#define GRID    (148 * NCTA)           // 1480: exactly one full wave
#define TOT_THREADS (GRID * THREADS)   // 189440

__device__ double   g_partial[GRID];
__device__ unsigned g_count = 0;       // self-resetting across graph replays

#define KS2 (42u ^ 0x1BD11BDAu)

__device__ __forceinline__ uint32_t rotl(uint32_t x, int r) {
    return __funnelshift_l(x, x, r);
}

// Threefry-2x32, key=(0,42), counters (x0, x1=x0+NE+42 pre-injected).
// Plain C adds; ptxas balances IADD3/IMAD across the alu/fma pipes and can
// fuse "x1 += kb; x0 = x0 + ka + x1" into IADD3.
__device__ __forceinline__ uint2 threefry(uint32_t x0, uint32_t x1) {
#define R(r) { x0 += x1; x1 = rotl(x1, r) ^ x0; }
    R(13) R(15) R(26) R(6)
    x1 += KS2 + 1u;  x0 = x0 + 42u + x1;  x1 = rotl(x1, 17) ^ x0;
    R(29) R(16) R(24)
    x1 += 2u;        x0 = x0 + KS2 + x1;  x1 = rotl(x1, 13) ^ x0;
    R(15) R(26) R(6)
    x1 += 45u;       x0 = x0 + x1;        x1 = rotl(x1, 17) ^ x0;
    R(29) R(16) R(24)
    x1 += KS2 + 4u;  x0 = x0 + 42u + x1;  x1 = rotl(x1, 13) ^ x0;
    R(15) R(26) R(6)
    return make_uint2(x0 + KS2, x1 + 5u);
#undef R
}

// JAX uniform bits->mantissa in ONE fma-pipe instruction:
//   hi(bits * 2^23) + 0x3f800000  ==  (bits >> 9) | 0x3f800000
// (fields disjoint, so add == or). Tiny-clamp dropped (fires w.p. 2^-23; the
// resulting -inf log2 resolves the comparison identically except on
// measure-~1e-10 joint events).
__device__ __forceinline__ float u01(uint32_t bits, uint32_t expo) {
    uint32_t m;
    asm("mad.hi.u32 %0, %1, %2, %3;" : "=r"(m) : "r"(bits), "n"(1u << 23), "r"(expo));
    return __uint_as_float(m) - 1.0f;
}

// Contribution of one element, in log2 units (scaled by ln2 once at the end).
// e = {r = q0/q1, qt(adj_t=0), qt(adj_t=1), unused}
__device__ __forceinline__ float elem(uint32_t bits0, uint32_t bits1,
                                      float4 e, float qav, uint32_t expo)
{
    const float lg0 = __log2f(u01(bits0, expo));
    const float lg1 = __log2f(u01(bits1, expo));
    // adj_t = 1  iff  q1*(-log u0) > q0*(-log u1)  <=>  lg0 < r*lg1  (lg's <= 0)
    const float qt  = (lg0 < e.x * lg1) ? e.z : e.y;
    const float l2p = __log2f(qav);          // -100 clamps never fire: qa in [1e-4, 1-1e-4]
    const float l2m = __log2f(1.0f - qav);
    return fmaf(qt, l2p - l2m, l2m);         // qt*l2p + (1-qt)*l2m
}

__global__ void __launch_bounds__(THREADS, NCTA)
diffusion_main(const int* __restrict__ adj, const int* __restrict__ t,
               const float* __restrict__ qa, const float* __restrict__ Qt,
               float* __restrict__ out)
{
    // Per-(b, a0) precomputed table: r = q0/q1, c0 = qt(adj_t=0), c1 = qt(adj_t=1).
    __shared__ float4 sTab[32];
    if (threadIdx.x < 32) {
        const int b  = threadIdx.x >> 1;
        const int a0 = threadIdx.x & 1;
        const int tb  = t[b];
        const int tm1 = tb ? (tb - 1) : (T_DIM - 1);   // JAX wraps t-1 = -1 -> T-1
        const float q0 = Qt[tb * 4 + a0 * 2 + 0];
        const float q1 = Qt[tb * 4 + a0 * 2 + 1];
        const float p0 = Qt[tm1 * 4 + a0 * 2 + 0];     // prior: Qt[t-1][a0][0]
        const float L00 = Qt[0];                       // Qt[0][0][0]
        const float L10 = Qt[2];                       // Qt[0][1][0]
        sTab[threadIdx.x] = make_float4(q0 / q1, L00 * p0 / q0, L10 * p0 / q1, 0.0f);
    }
    __syncthreads();

    const uint32_t expo = 0x3f800000u;

    const int4*   adj4 = (const int4*)adj;
    const float4* qa4  = (const float4*)qa;

    float a0v = 0.0f, a1v = 0.0f, a2v = 0.0f, a3v = 0.0f;

    // Grid-stride over int4-groups of the low half; exactly one wave resident.
    #pragma unroll 1
    for (unsigned i = (unsigned)blockIdx.x * THREADS + threadIdx.x; i < HQ;
         i += TOT_THREADS) {
        // 128-bit loads first; ~550 threefry instrs hide them.
        const int4   alo = adj4[i];
        const int4   ahi = adj4[i + HQ];
        const float4 qlo = qa4[i];
        const float4 qhi = qa4[i + HQ];

        // Exact JAX counter mapping (validated):
        // low elem e = 4i+m uses y0 of calls (2e, 2e+NE), (2e+1, 2e+1+NE);
        // high elem e+HALF uses y1 of the same two calls. 1 call/element.
        const uint32_t c8 = i * 8u;
        const uint2 r0 = threefry(c8 + 0u, c8 + (NE + 42u + 0u));
        const uint2 r1 = threefry(c8 + 1u, c8 + (NE + 42u + 1u));
        const uint2 r2 = threefry(c8 + 2u, c8 + (NE + 42u + 2u));
        const uint2 r3 = threefry(c8 + 3u, c8 + (NE + 42u + 3u));
        const uint2 r4 = threefry(c8 + 4u, c8 + (NE + 42u + 4u));
        const uint2 r5 = threefry(c8 + 5u, c8 + (NE + 42u + 5u));
        const uint2 r6 = threefry(c8 + 6u, c8 + (NE + 42u + 6u));
        const uint2 r7 = threefry(c8 + 7u, c8 + (NE + 42u + 7u));

        // All 4 low elems share b (4i..4i+3 never cross a 2^20 boundary).
        const unsigned b2 = (i >> 18) * 2u;   // b_lo = (4i)>>20; key = b*2 + a0
        a0v += elem(r0.x, r1.x, sTab[b2 +       (unsigned)alo.x], qlo.x, expo);
        a1v += elem(r2.x, r3.x, sTab[b2 +       (unsigned)alo.y], qlo.y, expo);
        a2v += elem(r4.x, r5.x, sTab[b2 +       (unsigned)alo.z], qlo.z, expo);
        a3v += elem(r6.x, r7.x, sTab[b2 +       (unsigned)alo.w], qlo.w, expo);
        // b for (e + HALF) is b_lo + 8  ->  table offset +16
        a0v += elem(r0.y, r1.y, sTab[b2 + 16u + (unsigned)ahi.x], qhi.x, expo);
        a1v += elem(r2.y, r3.y, sTab[b2 + 16u + (unsigned)ahi.y], qhi.y, expo);
        a2v += elem(r4.y, r5.y, sTab[b2 + 16u + (unsigned)ahi.z], qhi.z, expo);
        a3v += elem(r6.y, r7.y, sTab[b2 + 16u + (unsigned)ahi.w], qhi.w, expo);
    }
    float acc = (a0v + a1v) + (a2v + a3v);

    // ---- deterministic in-kernel reduction ----
    #pragma unroll
    for (int off = 16; off > 0; off >>= 1)
        acc += __shfl_down_sync(0xffffffffu, acc, off);

    __shared__ float wsum[THREADS / 32];
    if ((threadIdx.x & 31) == 0) wsum[threadIdx.x >> 5] = acc;
    __syncthreads();

    __shared__ bool isLast;
    if (threadIdx.x == 0) {
        double s = 0.0;
        #pragma unroll
        for (int w = 0; w < THREADS / 32; w++) s += (double)wsum[w];
        g_partial[blockIdx.x] = s;
        __threadfence();
        isLast = (atomicAdd(&g_count, 1u) == GRID - 1u);
    }
    __syncthreads();

    if (isLast) {
        __threadfence();  // acquire: all g_partial writes visible
        double s = 0.0;
        for (int i2 = threadIdx.x; i2 < GRID; i2 += THREADS) s += g_partial[i2];
        __shared__ double sh[THREADS];
        sh[threadIdx.x] = s;
        __syncthreads();
        #pragma unroll
        for (int off = THREADS / 2; off > 0; off >>= 1) {
            if (threadIdx.x < off) sh[threadIdx.x] += sh[threadIdx.x + off];
            __syncthreads();
        }
        if (threadIdx.x == 0) {
            // accumulated in log2 units -> scale by ln2; loss = -mean
            out[0] = (float)(-(sh[0] * 0.69314718055994530942) / (double)NE);
            g_count = 0;   // reset for next graph replay
        }
    }
}

extern "C" void kernel_launch(void* const* d_in, const int* in_sizes, int n_in,
                              void* d_out, int out_size)
{
    const int*   adj = (const int*)d_in[0];    // adj_start [B,N,N] int32
    const int*   t   = (const int*)d_in[1];    // t [B] int32
    const float* qa  = (const float*)d_in[2];  // q_approx [B*N*N] float32
    const float* Qt  = (const float*)d_in[3];  // Qt [T,2,2] float32
    float* out = (float*)d_out;

    diffusion_main<<<GRID, THREADS>>>(adj, t, qa, Qt, out);
}

// round 11
// speedup vs baseline: 1.1320x; 1.1320x over previous
#include <cuda_runtime.h>
#include <cstdint>

// Problem constants (fixed by the reference).
#define T_DIM 100
#define NE    16777216u      // B*N*N
#define HALF  8388608u       // NE/2
#define HQ    2097152u       // HALF/4  (int4-index space of the low half)

#define THREADS 128
#define GRID    4096
#define TOT_THREADS (GRID * THREADS)   // 524288 = 2^19
#define ITERS   4                      // exact: HQ / TOT_THREADS

__device__ double   g_partial[GRID];
__device__ unsigned g_count = 0;       // self-resetting across graph replays

#define KS2 (42u ^ 0x1BD11BDAu)
#define C1  (NE + 42u)                 // folded first key injection

__device__ __forceinline__ uint32_t rotl(uint32_t x, int r) {
    return __funnelshift_l(x, x, r);
}

// Threefry-2x32, key=(0,42). Caller passes the POST-round-1-add state:
//   x0 = (c+k) + (c+k+C1)  (precomputed as s + 2k, s = 2c + C1)
//   x1 = c + k + C1        (pre-rotation value)
// so round 1 starts directly at the rotl. Plain C adds; ptxas fuses the
// "x1 += kb; x0 = x0 + ka + x1" injection pattern into IADD3 and balances
// IADD3/IMAD across the alu/fma pipes.
__device__ __forceinline__ uint2 threefry(uint32_t x0, uint32_t x1) {
#define R(r) { x0 += x1; x1 = rotl(x1, r) ^ x0; }
    x1 = rotl(x1, 13) ^ x0;            // tail of round 1 (add done by caller)
    R(15) R(26) R(6)
    x1 += KS2 + 1u;  x0 = x0 + 42u + x1;  x1 = rotl(x1, 17) ^ x0;
    R(29) R(16) R(24)
    x1 += 2u;        x0 = x0 + KS2 + x1;  x1 = rotl(x1, 13) ^ x0;
    R(15) R(26) R(6)
    x1 += 45u;       x0 = x0 + x1;        x1 = rotl(x1, 17) ^ x0;
    R(29) R(16) R(24)
    x1 += KS2 + 4u;  x0 = x0 + 42u + x1;  x1 = rotl(x1, 13) ^ x0;
    R(15) R(26) R(6)
    return make_uint2(x0 + KS2, x1 + 5u);
#undef R
}

// JAX uniform bits->mantissa in ONE fma-pipe instruction:
//   hi(bits * 2^23) + 0x3f800000  ==  (bits >> 9) | 0x3f800000
// (fields disjoint, so add == or). Tiny-clamp dropped (fires w.p. 2^-23; the
// resulting -inf log2 resolves the comparison identically except on
// measure-~1e-10 joint events).
__device__ __forceinline__ float u01(uint32_t bits, uint32_t expo) {
    uint32_t m;
    asm("mad.hi.u32 %0, %1, %2, %3;" : "=r"(m) : "r"(bits), "n"(1u << 23), "r"(expo));
    return __uint_as_float(m) - 1.0f;
}

// Contribution of one element, in log2 units (scaled by ln2 once at the end).
// e = {r = q0/q1, qt(adj_t=0), qt(adj_t=1), unused}
__device__ __forceinline__ float elem(uint32_t bits0, uint32_t bits1,
                                      float4 e, float qav, uint32_t expo)
{
    const float lg0 = __log2f(u01(bits0, expo));
    const float lg1 = __log2f(u01(bits1, expo));
    // adj_t = 1  iff  q1*(-log u0) > q0*(-log u1)  <=>  lg0 < r*lg1  (lg's <= 0)
    const float qt  = (lg0 < e.x * lg1) ? e.z : e.y;
    const float l2p = __log2f(qav);          // -100 clamps never fire: qa in [1e-4, 1-1e-4]
    const float l2m = __log2f(1.0f - qav);
    return fmaf(qt, l2p - l2m, l2m);         // qt*l2p + (1-qt)*l2m
}

__global__ void __launch_bounds__(THREADS, 9)
diffusion_main(const int* __restrict__ adj, const int* __restrict__ t,
               const float* __restrict__ qa, const float* __restrict__ Qt,
               float* __restrict__ out)
{
    // Per-(b, a0) precomputed table: r = q0/q1, c0 = qt(adj_t=0), c1 = qt(adj_t=1).
    __shared__ float4 sTab[32];
    if (threadIdx.x < 32) {
        const int b  = threadIdx.x >> 1;
        const int a0 = threadIdx.x & 1;
        const int tb  = t[b];
        const int tm1 = tb ? (tb - 1) : (T_DIM - 1);   // JAX wraps t-1 = -1 -> T-1
        const float q0 = Qt[tb * 4 + a0 * 2 + 0];
        const float q1 = Qt[tb * 4 + a0 * 2 + 1];
        const float p0 = Qt[tm1 * 4 + a0 * 2 + 0];     // prior: Qt[t-1][a0][0]
        const float L00 = Qt[0];                       // Qt[0][0][0]
        const float L10 = Qt[2];                       // Qt[0][1][0]
        sTab[threadIdx.x] = make_float4(q0 / q1, L00 * p0 / q0, L10 * p0 / q1, 0.0f);
    }
    __syncthreads();

    const uint32_t expo = 0x3f800000u;

    const int4*   adj4 = (const int4*)adj;
    const float4* qa4  = (const float4*)qa;

    float a0v = 0.0f, a1v = 0.0f, a2v = 0.0f, a3v = 0.0f;
    unsigned i = (unsigned)blockIdx.x * THREADS + threadIdx.x;

    #pragma unroll 1
    for (int it = 0; it < ITERS; ++it, i += TOT_THREADS) {
        // 128-bit loads first; ~550 threefry instrs hide them.
        const int4   alo = adj4[i];
        const int4   ahi = adj4[i + HQ];
        const float4 qlo = qa4[i];
        const float4 qhi = qa4[i + HQ];

        // Exact JAX counter mapping (validated):
        // low elem e = 4i+m uses y0 of calls (2e, 2e+NE), (2e+1, 2e+1+NE);
        // high elem e+HALF uses y1 of the same two calls. 1 call/element.
        // Counter folding: call k gets x1 = c8 + C1 + k, x0(post-r1) = s + 2k,
        // with c8 = 8i, s = 2*c8 + C1 = 16i + C1.
        const uint32_t c8 = i * 8u;
        const uint32_t s  = i * 16u + C1;
        const uint2 r0 = threefry(s + 0u,  c8 + (C1 + 0u));
        const uint2 r1 = threefry(s + 2u,  c8 + (C1 + 1u));
        const uint2 r2 = threefry(s + 4u,  c8 + (C1 + 2u));
        const uint2 r3 = threefry(s + 6u,  c8 + (C1 + 3u));
        const uint2 r4 = threefry(s + 8u,  c8 + (C1 + 4u));
        const uint2 r5 = threefry(s + 10u, c8 + (C1 + 5u));
        const uint2 r6 = threefry(s + 12u, c8 + (C1 + 6u));
        const uint2 r7 = threefry(s + 14u, c8 + (C1 + 7u));

        // All 4 low elems share b (4i..4i+3 never cross a 2^20 boundary).
        const unsigned b2 = (i >> 18) * 2u;   // b_lo = (4i)>>20; key = b*2 + a0
        a0v += elem(r0.x, r1.x, sTab[b2 +       (unsigned)alo.x], qlo.x, expo);
        a1v += elem(r2.x, r3.x, sTab[b2 +       (unsigned)alo.y], qlo.y, expo);
        a2v += elem(r4.x, r5.x, sTab[b2 +       (unsigned)alo.z], qlo.z, expo);
        a3v += elem(r6.x, r7.x, sTab[b2 +       (unsigned)alo.w], qlo.w, expo);
        // b for (e + HALF) is b_lo + 8  ->  table offset +16
        a0v += elem(r0.y, r1.y, sTab[b2 + 16u + (unsigned)ahi.x], qhi.x, expo);
        a1v += elem(r2.y, r3.y, sTab[b2 + 16u + (unsigned)ahi.y], qhi.y, expo);
        a2v += elem(r4.y, r5.y, sTab[b2 + 16u + (unsigned)ahi.z], qhi.z, expo);
        a3v += elem(r6.y, r7.y, sTab[b2 + 16u + (unsigned)ahi.w], qhi.w, expo);
    }
    float acc = (a0v + a1v) + (a2v + a3v);

    // ---- deterministic in-kernel reduction ----
    #pragma unroll
    for (int off = 16; off > 0; off >>= 1)
        acc += __shfl_down_sync(0xffffffffu, acc, off);

    __shared__ float wsum[THREADS / 32];
    if ((threadIdx.x & 31) == 0) wsum[threadIdx.x >> 5] = acc;
    __syncthreads();

    __shared__ bool isLast;
    if (threadIdx.x == 0) {
        double s = 0.0;
        #pragma unroll
        for (int w = 0; w < THREADS / 32; w++) s += (double)wsum[w];
        g_partial[blockIdx.x] = s;
        __threadfence();
        isLast = (atomicAdd(&g_count, 1u) == GRID - 1u);
    }
    __syncthreads();

    if (isLast) {
        __threadfence();  // acquire: all g_partial writes visible
        double s = 0.0;
        for (int i2 = threadIdx.x; i2 < GRID; i2 += THREADS) s += g_partial[i2];
        __shared__ double sh[THREADS];
        sh[threadIdx.x] = s;
        __syncthreads();
        #pragma unroll
        for (int off = THREADS / 2; off > 0; off >>= 1) {
            if (threadIdx.x < off) sh[threadIdx.x] += sh[threadIdx.x + off];
            __syncthreads();
        }
        if (threadIdx.x == 0) {
            // accumulated in log2 units -> scale by ln2; loss = -mean
            out[0] = (float)(-(sh[0] * 0.69314718055994530942) / (double)NE);
            g_count = 0;   // reset for next graph replay
        }
    }
}

extern "C" void kernel_launch(void* const* d_in, const int* in_sizes, int n_in,
                              void* d_out, int out_size)
{
    const int*   adj = (const int*)d_in[0];    // adj_start [B,N,N] int32
    const int*   t   = (const int*)d_in[1];    // t [B] int32
    const float* qa  = (const float*)d_in[2];  // q_approx [B*N*N] float32
    const float* Qt  = (const float*)d_in[3];  // Qt [T,2,2] float32
    float* out = (float*)d_out;

    diffusion_main<<<GRID, THREADS>>>(adj, t, qa, Qt, out);
}